// round 12
// baseline (speedup 1.0000x reference)
#include <cuda_runtime.h>
#include <math.h>

#define B_  64
#define T_  512
#define I_  1024
#define H_  1024
#define M_  (B_*T_)

typedef unsigned long long ull;

// ---------------------------------------------------------------------------
// f32x2 packed helpers (sm_103a FFMA2/FADD2 — only reachable via PTX)
// ---------------------------------------------------------------------------
__device__ __forceinline__ ull ffma2(ull a, ull b, ull c) {
    ull d;
    asm("fma.rn.f32x2 %0, %1, %2, %3;" : "=l"(d) : "l"(a), "l"(b), "l"(c));
    return d;
}
__device__ __forceinline__ ull fadd2(ull a, ull b) {
    ull d;
    asm("add.rn.f32x2 %0, %1, %2;" : "=l"(d) : "l"(a), "l"(b));
    return d;
}
__device__ __forceinline__ ull splat2(float x) {
    ull r;
    asm("mov.b64 %0, {%1, %1};" : "=l"(r) : "f"(x));
    return r;
}

// ---------------------------------------------------------------------------
// Scratch (device globals — no allocation allowed)
// ---------------------------------------------------------------------------
__device__ float g_xt[T_][I_][B_];     // transposed x: [t][k][b]  (128 MB)
__device__ float g_ht[2][H_][B_];      // transposed h double buffer [buf][k][b]
__device__ unsigned g_cnt[2];          // per-batch-half barrier counters
__device__ volatile unsigned g_gen[2]; // monotonic generations (replay-safe)

#define SCAN_BLOCKS  128
#define GROUP_BLOCKS 64

// ---------------------------------------------------------------------------
// Kernel T: transpose x[b][t][i] -> g_xt[t][i][b]. 32x32 tiles.
// ---------------------------------------------------------------------------
__global__ __launch_bounds__(256)
void transpose_x_kernel(const float* __restrict__ x) {
    __shared__ float tile[32][33];
    const int tx = threadIdx.x;
    const int ty = threadIdx.y;
    const int i0 = blockIdx.x * 32;
    const int b0 = blockIdx.y * 32;
    const int t  = blockIdx.z;

#pragma unroll
    for (int r = ty; r < 32; r += 8)
        tile[r][tx] = x[(size_t)(b0 + r) * T_ * I_ + (size_t)t * I_ + i0 + tx];
    __syncthreads();
#pragma unroll
    for (int r = ty; r < 32; r += 8)
        g_xt[t][i0 + r][b0 + tx] = tile[tx][r];
}

// ---------------------------------------------------------------------------
// Kernel S: fused persistent scan, merged accumulation, CONFLICT-FREE smem.
// 128 blocks x 256 threads, 1 block/SM. Block (bh, cg): batches [bh*32,+32),
// cols [cg*16,+16). Lane l = k4*8 + cgl*4 + bg; warp w: k in [w*128,+128).
// Lane register tile: 8b x 8c = 32 f32x2 accumulators.
//
// Bank-conflict fix: k4 slices are 32 rows apart and 32*KT_STRIDE ≡ 0 mod 32
// banks, so a naive walk 4-way-conflicts every U_t/W_t LDS.128. Each k4 group
// walks its slice with phase s(k4) ∈ {0,5,4,1} (ii = (i+s)&31): U-quad =
// (5(i+s) + 2cgl) mod 8 -> {0,1,4,5}⊕{0,2} = all 8 quads -> conflict-free.
// s depends only on k4, so h-LDG coalescing is unchanged.
//
// Per step tau (one reduction):
//   X-kloop (acc = W x_tau, barrier-independent) -> wait -> H-kloop
//   (acc += U h_{tau-1}) -> single reduce -> tanh -> stores -> arrive.
// ---------------------------------------------------------------------------
#define KT_STRIDE 20
#define KT_FLOATS (H_ * KT_STRIDE)                  // 80 KB
#define RED_OFF   (2 * KT_FLOATS)
#define RED_FLOATS (8 * 512)                        // 16 KB
#define CF_OFF    (RED_OFF + RED_FLOATS)
#define SCAN_SMEM ((CF_OFF + 512) * sizeof(float))  // ~178.5 KB

__global__ __launch_bounds__(256, 1)
void scan_kernel(float* __restrict__ out, const float* __restrict__ U,
                 const float* __restrict__ bU, const float* __restrict__ W,
                 const float* __restrict__ bW) {
    extern __shared__ float smem[];
    float* U_t = smem;                  // [1024][20] (16 used)
    float* W_t = smem + KT_FLOATS;      // [1024][20]
    float* red = smem + RED_OFF;        // [8][512]   [w][c*32+b]
    float* C_f = smem + CF_OFF;         // [16][32]

    const int tid = threadIdx.x;
    const int l   = tid & 31;
    const int w   = tid >> 5;
    const int bh  = blockIdx.x & 1;
    const int cg  = blockIdx.x >> 1;          // 0..63
    const int k4  = l >> 3;
    const int cgl = (l >> 2) & 1;
    const int bg  = l & 3;
    const int kbase  = w * 128 + k4 * 32;
    const int sphase = (0x1450 >> (k4 * 4)) & 7;   // {0,5,4,1} for k4=0..3

    // epilogue mappings
    const int c7 = tid >> 4;                  // 0..15 (owner col)
    const int b7 = (tid & 15) * 2;            // 0..30 (owner batch pair)
    const int b9 = tid >> 3;                  // 0..31 (store batch)
    const int c9 = (tid & 7) * 2;             // 0..14 (store col pair)

    // one-time: transpose U and W slices into smem
    for (int idx = tid; idx < 16 * H_; idx += 256) {
        int c = idx >> 10;
        int k = idx & (H_ - 1);
        U_t[k * KT_STRIDE + c] = U[(size_t)(cg * 16 + c) * H_ + k];
        W_t[k * KT_STRIDE + c] = W[(size_t)(cg * 16 + c) * I_ + k];
    }
    const float bWc = bW[cg * 16 + c7];
    const float bSc = bWc + bU[cg * 16 + c7];   // combined bias for tau>=1
    __syncthreads();

    const float* urow0 = U_t + kbase * KT_STRIDE + cgl * 8;
    const float* wrow0 = W_t + kbase * KT_STRIDE + cgl * 8;
    const int bB  = bh * 32 + bg * 8;
    const int n9  = cg * 16 + c9;
    const int bg9 = bh * 32 + b9;
    float* o9 = out + (size_t)bg9 * T_ * H_ + n9;

    ull acc[8][4];
    unsigned my_gen = 0;

// ---- macro: accumulate one k-slice matvec into acc (phase-rotated walk) ---
#define KLOOP(SRCROW, UWROW)                                                  \
    {                                                                         \
        const float* srow_ = (SRCROW);                                        \
        const float* mrow_ = (UWROW);                                         \
        _Pragma("unroll 8")                                                   \
        for (int i = 0; i < 32; ++i) {                                        \
            const int ii = (i + sphase) & 31;                                 \
            const ulonglong2* hp = (const ulonglong2*)(srow_ + ii * B_);      \
            ulonglong2 hA = __ldcg(hp);                                       \
            ulonglong2 hB = __ldcg(hp + 1);                                   \
            const float* up = mrow_ + ii * KT_STRIDE;                         \
            float4 u0 = *(const float4*)up;                                   \
            float4 u1 = *(const float4*)(up + 4);                             \
            float uf[8] = {u0.x, u0.y, u0.z, u0.w, u1.x, u1.y, u1.z, u1.w};   \
            _Pragma("unroll")                                                 \
            for (int c = 0; c < 8; ++c) {                                     \
                ull s = splat2(uf[c]);                                        \
                acc[c][0] = ffma2(hA.x, s, acc[c][0]);                        \
                acc[c][1] = ffma2(hA.y, s, acc[c][1]);                        \
                acc[c][2] = ffma2(hB.x, s, acc[c][2]);                        \
                acc[c][3] = ffma2(hB.y, s, acc[c][3]);                        \
            }                                                                 \
        }                                                                     \
    }

// ---- macro: in-warp butterfly + smem partials -----------------------------
#define REDUCE_TO_SMEM()                                                      \
    {                                                                         \
        _Pragma("unroll")                                                     \
        for (int c = 0; c < 8; ++c)                                           \
            _Pragma("unroll")                                                 \
            for (int p = 0; p < 4; ++p) {                                     \
                acc[c][p] = fadd2(acc[c][p],                                  \
                    __shfl_xor_sync(0xffffffffu, acc[c][p], 8));              \
                acc[c][p] = fadd2(acc[c][p],                                  \
                    __shfl_xor_sync(0xffffffffu, acc[c][p], 16));             \
            }                                                                 \
        if (l < 8) {                                                          \
            float* rw = red + w * 512;                                        \
            _Pragma("unroll")                                                 \
            for (int c = 0; c < 8; ++c)                                       \
                _Pragma("unroll")                                             \
                for (int p = 0; p < 4; ++p)                                   \
                    *(ull*)&rw[(cgl * 8 + c) * 32 + bg * 8 + 2 * p] =         \
                        acc[c][p];                                            \
        }                                                                     \
    }

#define ARRIVE()                                                              \
    if (tid == 0) {                                                           \
        __threadfence();                                                      \
        my_gen = g_gen[bh];                                                   \
        if (atomicAdd(&g_cnt[bh], 1u) == GROUP_BLOCKS - 1) {                  \
            atomicExch(&g_cnt[bh], 0u);                                       \
            __threadfence();                                                  \
            g_gen[bh] = my_gen + 1;                                           \
        }                                                                     \
    }

    // ======================= tau = 0 prologue ==============================
    {
#pragma unroll
        for (int c = 0; c < 8; ++c)
#pragma unroll
            for (int p = 0; p < 4; ++p) acc[c][p] = 0ull;
        KLOOP(&g_xt[0][kbase][bB], wrow0);
        REDUCE_TO_SMEM();
        __syncthreads();
        float s0 = 0.f, s1 = 0.f;
#pragma unroll
        for (int w8 = 0; w8 < 8; ++w8) {
            float2 v = *(const float2*)&red[w8 * 512 + c7 * 32 + b7];
            s0 += v.x; s1 += v.y;
        }
        float h0 = tanhf(s0 + bWc);
        float h1 = tanhf(s1 + bWc);
        int n  = cg * 16 + c7;
        int b0 = bh * 32 + b7;
        *(float2*)&g_ht[0][n][b0] = make_float2(h0, h1);
        C_f[c7 * 32 + b7]     = h0;
        C_f[c7 * 32 + b7 + 1] = h1;
        __syncthreads();
        ARRIVE();
        float2 o = make_float2(C_f[c9 * 32 + b9], C_f[(c9 + 1) * 32 + b9]);
        *(float2*)o9 = o;
    }

    // ======================= main loop tau = 1..511 ========================
    for (int tau = 1; tau < T_; ++tau) {
        // phase X: acc = W x[:,tau,:] partials (no barrier dependency)
#pragma unroll
        for (int c = 0; c < 8; ++c)
#pragma unroll
            for (int p = 0; p < 4; ++p) acc[c][p] = 0ull;
        KLOOP(&g_xt[tau][kbase][bB], wrow0);

        // barrier wait: h_{tau-1} visible
        if (tid == 0) {
            while (g_gen[bh] == my_gen) { }
            __threadfence();
        }
        __syncthreads();                       // S1 (also protects red reuse)

        // phase H: acc += U h_{tau-1} (same k-partition -> merged reduce)
        KLOOP(&g_ht[(tau - 1) & 1][kbase][bB], urow0);

        REDUCE_TO_SMEM();
        __syncthreads();                       // S2

        {
            float s0 = 0.f, s1 = 0.f;
#pragma unroll
            for (int w8 = 0; w8 < 8; ++w8) {
                float2 v = *(const float2*)&red[w8 * 512 + c7 * 32 + b7];
                s0 += v.x; s1 += v.y;
            }
            float h0 = tanhf(s0 + bSc);
            float h1 = tanhf(s1 + bSc);
            int n  = cg * 16 + c7;
            int b0 = bh * 32 + b7;
            *(float2*)&g_ht[tau & 1][n][b0] = make_float2(h0, h1);
            C_f[c7 * 32 + b7]     = h0;
            C_f[c7 * 32 + b7 + 1] = h1;
        }
        __syncthreads();                       // S3: g_ht + C_f visible

        // arrive ASAP (next step's enabling event)
        if (tau < T_ - 1) { ARRIVE(); }

        // coalesced out1 (+out2) store, off the critical path
        float2 o = make_float2(C_f[c9 * 32 + b9], C_f[(c9 + 1) * 32 + b9]);
        *(float2*)(o9 + (size_t)tau * H_) = o;
        if (tau == T_ - 1)
            *(float2*)(out + (size_t)M_ * H_ + (size_t)bg9 * H_ + n9) = o;
    }

#undef KLOOP
#undef REDUCE_TO_SMEM
#undef ARRIVE
}

// ---------------------------------------------------------------------------
// Launch
// ---------------------------------------------------------------------------
extern "C" void kernel_launch(void* const* d_in, const int* in_sizes, int n_in,
                              void* d_out, int out_size) {
    const float* x  = (const float*)d_in[0];   // [B,T,I]
    const float* W  = (const float*)d_in[1];   // [H,I]
    const float* bW = (const float*)d_in[2];   // [H]
    const float* U  = (const float*)d_in[3];   // [H,H]
    const float* bU = (const float*)d_in[4];   // [H]
    float* out = (float*)d_out;                // out1 [B*T*H] ++ out2 [B*H]

    dim3 tb(32, 8);
    dim3 tg(I_ / 32, B_ / 32, T_);   // (32, 2, 512)
    transpose_x_kernel<<<tg, tb>>>(x);

    cudaFuncSetAttribute(scan_kernel, cudaFuncAttributeMaxDynamicSharedMemorySize,
                         (int)SCAN_SMEM);
    scan_kernel<<<SCAN_BLOCKS, 256, SCAN_SMEM>>>(out, U, bU, W, bW);
}

// round 13
// speedup vs baseline: 1.7595x; 1.7595x over previous
#include <cuda_runtime.h>
#include <math.h>

#define B_  64
#define T_  512
#define I_  1024
#define H_  1024
#define M_  (B_*T_)

typedef unsigned long long ull;

// ---------------------------------------------------------------------------
// f32x2 packed helpers (sm_103a FFMA2/FADD2 — only reachable via PTX)
// ---------------------------------------------------------------------------
__device__ __forceinline__ ull ffma2(ull a, ull b, ull c) {
    ull d;
    asm("fma.rn.f32x2 %0, %1, %2, %3;" : "=l"(d) : "l"(a), "l"(b), "l"(c));
    return d;
}
__device__ __forceinline__ ull fadd2(ull a, ull b) {
    ull d;
    asm("add.rn.f32x2 %0, %1, %2;" : "=l"(d) : "l"(a), "l"(b));
    return d;
}
__device__ __forceinline__ ull splat2(float x) {
    ull r;
    asm("mov.b64 %0, {%1, %1};" : "=l"(r) : "f"(x));
    return r;
}

// ---------------------------------------------------------------------------
// Scratch (device globals — no allocation allowed)
// ---------------------------------------------------------------------------
__device__ float g_xt[T_][I_][B_];     // transposed x: [t][k][b]  (128 MB)
__device__ float g_ht[2][H_][B_];      // transposed h double buffer [buf][k][b]
__device__ unsigned g_flag[2][64 * 8]; // per-block progress flags (32B apart),
                                       // monotonic across graph replays

#define SCAN_BLOCKS  128
#define GROUP_BLOCKS 64

// ---------------------------------------------------------------------------
// Kernel T: transpose x[b][t][i] -> g_xt[t][i][b]. 32x32 tiles.
// ---------------------------------------------------------------------------
__global__ __launch_bounds__(256)
void transpose_x_kernel(const float* __restrict__ x) {
    __shared__ float tile[32][33];
    const int tx = threadIdx.x;
    const int ty = threadIdx.y;
    const int i0 = blockIdx.x * 32;
    const int b0 = blockIdx.y * 32;
    const int t  = blockIdx.z;

#pragma unroll
    for (int r = ty; r < 32; r += 8)
        tile[r][tx] = x[(size_t)(b0 + r) * T_ * I_ + (size_t)t * I_ + i0 + tx];
    __syncthreads();
#pragma unroll
    for (int r = ty; r < 32; r += 8)
        g_xt[t][i0 + r][b0 + tx] = tile[tx][r];
}

// ---------------------------------------------------------------------------
// Kernel S: fused persistent scan, merged accumulation, distributed flags.
// 128 blocks x 256 threads, 1 block/SM. Block (bh, cg): batches [bh*32,+32),
// cols [cg*16,+16). Lane l = k4*8 + cgl*4 + bg; warp w: k in [w*128,+128).
// Lane register tile: 8b x 8c = 32 f32x2 accumulators.
//
// Synchronization (per batch-half group of 64 blocks):
//   - each block OWNS flag[bh][cg]; after writing h_tau it does ONE
//     st.release.gpu (orders all prior stores; no fence, no atomic).
//   - wait: threads tid<64 poll all 64 peer flags in parallel with
//     ld.acquire.gpu; __syncthreads() broadcasts the acquire block-wide.
//   - flags grow monotonically (base+tau+1); base = own flag at entry, all
//     blocks write exactly 511 increments per launch -> replay-safe.
//
// Per step tau (one reduction):
//   X-kloop (acc = W x_tau, barrier-independent) -> wait -> H-kloop
//   (acc += U h_{tau-1}) -> single reduce -> tanh -> stores -> release.
// ---------------------------------------------------------------------------
#define KT_STRIDE 20
#define KT_FLOATS (H_ * KT_STRIDE)                  // 80 KB
#define RED_OFF   (2 * KT_FLOATS)
#define RED_FLOATS (8 * 512)                        // 16 KB
#define CF_OFF    (RED_OFF + RED_FLOATS)
#define BASE_OFF  (CF_OFF + 512)
#define SCAN_SMEM ((BASE_OFF + 8) * sizeof(float))  // ~178.5 KB

__global__ __launch_bounds__(256, 1)
void scan_kernel(float* __restrict__ out, const float* __restrict__ U,
                 const float* __restrict__ bU, const float* __restrict__ W,
                 const float* __restrict__ bW) {
    extern __shared__ float smem[];
    float* U_t = smem;                  // [1024][20] (16 used)
    float* W_t = smem + KT_FLOATS;      // [1024][20]
    float* red = smem + RED_OFF;        // [8][512]   [w][c*32+b]
    float* C_f = smem + CF_OFF;         // [16][32]

    const int tid = threadIdx.x;
    const int l   = tid & 31;
    const int w   = tid >> 5;
    const int bh  = blockIdx.x & 1;
    const int cg  = blockIdx.x >> 1;          // 0..63
    const int k4  = l >> 3;
    const int cgl = (l >> 2) & 1;
    const int bg  = l & 3;
    const int kbase = w * 128 + k4 * 32;

    // epilogue mappings
    const int c7 = tid >> 4;                  // 0..15 (owner col)
    const int b7 = (tid & 15) * 2;            // 0..30 (owner batch pair)
    const int b9 = tid >> 3;                  // 0..31 (store batch)
    const int c9 = (tid & 7) * 2;             // 0..14 (store col pair)

    // entry: read my OWN flag (only I write it) -> replay-safe base
    if (tid == 0) {
        unsigned v;
        asm volatile("ld.acquire.gpu.global.u32 %0, [%1];"
                     : "=r"(v) : "l"(&g_flag[bh][cg * 8]) : "memory");
        *(unsigned*)&smem[BASE_OFF] = v;
    }

    // one-time: transpose U and W slices into smem
    for (int idx = tid; idx < 16 * H_; idx += 256) {
        int c = idx >> 10;
        int k = idx & (H_ - 1);
        U_t[k * KT_STRIDE + c] = U[(size_t)(cg * 16 + c) * H_ + k];
        W_t[k * KT_STRIDE + c] = W[(size_t)(cg * 16 + c) * I_ + k];
    }
    const float bWc = bW[cg * 16 + c7];
    const float bSc = bWc + bU[cg * 16 + c7];   // combined bias for tau>=1
    __syncthreads();
    const unsigned base_r = *(const unsigned*)&smem[BASE_OFF];

    const float* urow0 = U_t + kbase * KT_STRIDE + cgl * 8;
    const float* wrow0 = W_t + kbase * KT_STRIDE + cgl * 8;
    const int bB  = bh * 32 + bg * 8;
    const int n9  = cg * 16 + c9;
    const int bg9 = bh * 32 + b9;
    float* o9 = out + (size_t)bg9 * T_ * H_ + n9;

    ull acc[8][4];

// ---- macro: accumulate one k-slice matvec into acc (linear walk) ----------
#define KLOOP(SRCROW, UWROW)                                                  \
    {                                                                         \
        const float* srow_ = (SRCROW);                                        \
        const float* mrow_ = (UWROW);                                         \
        _Pragma("unroll 16")                                                  \
        for (int i = 0; i < 32; ++i) {                                        \
            const ulonglong2* hp = (const ulonglong2*)(srow_ + i * B_);       \
            ulonglong2 hA = __ldcg(hp);                                       \
            ulonglong2 hB = __ldcg(hp + 1);                                   \
            const float* up = mrow_ + i * KT_STRIDE;                          \
            float4 u0 = *(const float4*)up;                                   \
            float4 u1 = *(const float4*)(up + 4);                             \
            float uf[8] = {u0.x, u0.y, u0.z, u0.w, u1.x, u1.y, u1.z, u1.w};   \
            _Pragma("unroll")                                                 \
            for (int c = 0; c < 8; ++c) {                                     \
                ull s = splat2(uf[c]);                                        \
                acc[c][0] = ffma2(hA.x, s, acc[c][0]);                        \
                acc[c][1] = ffma2(hA.y, s, acc[c][1]);                        \
                acc[c][2] = ffma2(hB.x, s, acc[c][2]);                        \
                acc[c][3] = ffma2(hB.y, s, acc[c][3]);                        \
            }                                                                 \
        }                                                                     \
    }

// ---- macro: in-warp butterfly + smem partials -----------------------------
#define REDUCE_TO_SMEM()                                                      \
    {                                                                         \
        _Pragma("unroll")                                                     \
        for (int c = 0; c < 8; ++c)                                           \
            _Pragma("unroll")                                                 \
            for (int p = 0; p < 4; ++p) {                                     \
                acc[c][p] = fadd2(acc[c][p],                                  \
                    __shfl_xor_sync(0xffffffffu, acc[c][p], 8));              \
                acc[c][p] = fadd2(acc[c][p],                                  \
                    __shfl_xor_sync(0xffffffffu, acc[c][p], 16));             \
            }                                                                 \
        if (l < 8) {                                                          \
            float* rw = red + w * 512;                                        \
            _Pragma("unroll")                                                 \
            for (int c = 0; c < 8; ++c)                                       \
                _Pragma("unroll")                                             \
                for (int p = 0; p < 4; ++p)                                   \
                    *(ull*)&rw[(cgl * 8 + c) * 32 + bg * 8 + 2 * p] =         \
                        acc[c][p];                                            \
        }                                                                     \
    }

// ---- flag release: orders all prior stores, no fence/atomic needed --------
#define RELEASE(VAL)                                                          \
    if (tid == 0) {                                                           \
        asm volatile("st.release.gpu.global.u32 [%0], %1;"                    \
                     :: "l"(&g_flag[bh][cg * 8]), "r"(VAL) : "memory");       \
    }

    // ======================= tau = 0 prologue ==============================
    {
#pragma unroll
        for (int c = 0; c < 8; ++c)
#pragma unroll
            for (int p = 0; p < 4; ++p) acc[c][p] = 0ull;
        KLOOP(&g_xt[0][kbase][bB], wrow0);
        REDUCE_TO_SMEM();
        __syncthreads();
        float s0 = 0.f, s1 = 0.f;
#pragma unroll
        for (int w8 = 0; w8 < 8; ++w8) {
            float2 v = *(const float2*)&red[w8 * 512 + c7 * 32 + b7];
            s0 += v.x; s1 += v.y;
        }
        float h0 = tanhf(s0 + bWc);
        float h1 = tanhf(s1 + bWc);
        int n  = cg * 16 + c7;
        int b0 = bh * 32 + b7;
        *(float2*)&g_ht[0][n][b0] = make_float2(h0, h1);
        C_f[c7 * 32 + b7]     = h0;
        C_f[c7 * 32 + b7 + 1] = h1;
        __syncthreads();
        RELEASE(base_r + 1u);
        float2 o = make_float2(C_f[c9 * 32 + b9], C_f[(c9 + 1) * 32 + b9]);
        *(float2*)o9 = o;
    }

    // ======================= main loop tau = 1..511 ========================
    for (int tau = 1; tau < T_; ++tau) {
        // phase X: acc = W x[:,tau,:] partials (no barrier dependency;
        // overlaps the whole inter-block flag window)
#pragma unroll
        for (int c = 0; c < 8; ++c)
#pragma unroll
            for (int p = 0; p < 4; ++p) acc[c][p] = 0ull;
        KLOOP(&g_xt[tau][kbase][bB], wrow0);

        // wait: all 64 peer flags must reach base+tau (h_{tau-1} released)
        {
            const unsigned tgt = base_r + (unsigned)tau;
            if (tid < GROUP_BLOCKS) {
                const unsigned* fp = &g_flag[bh][tid * 8];
                unsigned v;
                do {
                    asm volatile("ld.acquire.gpu.global.u32 %0, [%1];"
                                 : "=r"(v) : "l"(fp) : "memory");
                } while ((int)(v - tgt) < 0);
            }
            __syncthreads();                   // S1: acquire broadcast + red reuse
        }

        // phase H: acc += U h_{tau-1} (same k-partition -> merged reduce)
        KLOOP(&g_ht[(tau - 1) & 1][kbase][bB], urow0);

        REDUCE_TO_SMEM();
        __syncthreads();                       // S2

        {
            float s0 = 0.f, s1 = 0.f;
#pragma unroll
            for (int w8 = 0; w8 < 8; ++w8) {
                float2 v = *(const float2*)&red[w8 * 512 + c7 * 32 + b7];
                s0 += v.x; s1 += v.y;
            }
            float h0 = tanhf(s0 + bSc);
            float h1 = tanhf(s1 + bSc);
            int n  = cg * 16 + c7;
            int b0 = bh * 32 + b7;
            *(float2*)&g_ht[tau & 1][n][b0] = make_float2(h0, h1);
            C_f[c7 * 32 + b7]     = h0;
            C_f[c7 * 32 + b7 + 1] = h1;
        }
        __syncthreads();                       // S3: g_ht + C_f visible

        // release ASAP (next step's enabling event)
        if (tau < T_ - 1) { RELEASE(base_r + (unsigned)tau + 1u); }

        // coalesced out1 (+out2) store, off the critical path
        float2 o = make_float2(C_f[c9 * 32 + b9], C_f[(c9 + 1) * 32 + b9]);
        *(float2*)(o9 + (size_t)tau * H_) = o;
        if (tau == T_ - 1)
            *(float2*)(out + (size_t)M_ * H_ + (size_t)bg9 * H_ + n9) = o;
    }

#undef KLOOP
#undef REDUCE_TO_SMEM
#undef RELEASE
}

// ---------------------------------------------------------------------------
// Launch
// ---------------------------------------------------------------------------
extern "C" void kernel_launch(void* const* d_in, const int* in_sizes, int n_in,
                              void* d_out, int out_size) {
    const float* x  = (const float*)d_in[0];   // [B,T,I]
    const float* W  = (const float*)d_in[1];   // [H,I]
    const float* bW = (const float*)d_in[2];   // [H]
    const float* U  = (const float*)d_in[3];   // [H,H]
    const float* bU = (const float*)d_in[4];   // [H]
    float* out = (float*)d_out;                // out1 [B*T*H] ++ out2 [B*H]

    dim3 tb(32, 8);
    dim3 tg(I_ / 32, B_ / 32, T_);   // (32, 2, 512)
    transpose_x_kernel<<<tg, tb>>>(x);

    cudaFuncSetAttribute(scan_kernel, cudaFuncAttributeMaxDynamicSharedMemorySize,
                         (int)SCAN_SMEM);
    scan_kernel<<<SCAN_BLOCKS, 256, SCAN_SMEM>>>(out, U, bU, W, bW);
}